// round 13
// baseline (speedup 1.0000x reference)
#include <cuda_runtime.h>
#include <cstdint>

// FourierFFTLayer == identity (ifft(fft(x)).real, rel_err ~1.3e-7 << 1e-3).
// HBM-bound copy at the ~7.5 TB/s path-independent LTS ceiling (~94% of
// spec). Final probe: write-through stores (__stwt / st.global.wt) instead
// of evict-first (__stcs) — pushes write sectors straight toward DRAM
// without establishing L2 dirty residency, potentially freeing LTS slots
// for the read stream. Same winning shape otherwise: MLP=2/thread,
// 128 threads x 32768 blocks, __ldcs reads.

__global__ __launch_bounds__(128) void identity_copy_f4x2_wt(
    const float4* __restrict__ in, float4* __restrict__ out, int n4)
{
    int base = blockIdx.x * (blockDim.x * 2) + threadIdx.x;
    const int s = blockDim.x;

    if (base + s < n4) {
        float4 a = __ldcs(in + base);
        float4 b = __ldcs(in + base + s);
        __stwt(out + base,     a);
        __stwt(out + base + s, b);
    } else {
        #pragma unroll
        for (int k = 0; k < 2; k++) {
            int i = base + k * s;
            if (i < n4) __stwt(out + i, __ldcs(in + i));
        }
    }
}

__global__ __launch_bounds__(256) void identity_copy_tail(
    const float* __restrict__ in, float* __restrict__ out, int start, int n)
{
    int i = start + blockIdx.x * blockDim.x + threadIdx.x;
    if (i < n) out[i] = in[i];
}

extern "C" void kernel_launch(void* const* d_in, const int* in_sizes, int n_in,
                              void* d_out, int out_size)
{
    const float* x = (const float*)d_in[0];
    float* out = (float*)d_out;
    int n = in_sizes[0];           // 33,554,432 (8 * 4096 * 1024)

    int n4 = n / 4;                // 8,388,608 float4
    if (n4 > 0) {
        const int threads = 128;
        const int per_block = threads * 2;             // 256 float4 / block
        int blocks = (n4 + per_block - 1) / per_block; // 32768
        identity_copy_f4x2_wt<<<blocks, threads>>>(
            (const float4*)x, (float4*)out, n4);
    }
    int tail_start = n4 * 4;
    if (n - tail_start > 0) {
        identity_copy_tail<<<1, 256>>>(x, out, tail_start, n);
    }
}

// round 14
// speedup vs baseline: 1.0375x; 1.0375x over previous
#include <cuda_runtime.h>
#include <cstdint>

// FINAL — FourierFFTLayer_13657996001424 on GB300 (sm_103a).
//
// reference = ifft(fft(x)).real on real fp32 input == identity up to fp32
// FFT roundoff (measured rel_err 1.3e-7, tolerance 1e-3). Optimal kernel is
// a pure HBM-bandwidth-bound copy: 128 MB read + 128 MB write = 256 MB
// aggregate at ~7.48 TB/s (~94% of 8 TB/s spec), the chip's path-independent
// LTS ceiling.
//
// Design space exhaustively measured (13 rounds):
//   unroll x1/x2/x4/x8     -> U-curve, min at x2 (MLP vs occupancy tradeoff)
//   copy-engine memcpy     -> worse (same LTS cap, costlier node replay)
//   persistent one-wave    -> worse (static-partition straggler tail)
//   store policy .cs/default/.wt -> .cs wins (evict-first drains cleanly,
//                             keeps L2 write-buffer elasticity, no dirty-L2
//                             contention across graph replays)
//   block 128 vs 256       -> tie; 128 kept for finer CLC granularity
// Winner: MLP=2/thread, 128 threads x 32768 blocks, streaming .cs on both
// streams (zero reuse), guard-free fast path on the exact-divide shape.
// Kernel 36.0us, reproduced 4x.

__global__ __launch_bounds__(128) void identity_copy_f4x2_b128(
    const float4* __restrict__ in, float4* __restrict__ out, int n4)
{
    int base = blockIdx.x * (blockDim.x * 2) + threadIdx.x;
    const int s = blockDim.x;

    if (base + s < n4) {
        float4 a = __ldcs(in + base);
        float4 b = __ldcs(in + base + s);
        __stcs(out + base,     a);
        __stcs(out + base + s, b);
    } else {
        #pragma unroll
        for (int k = 0; k < 2; k++) {
            int i = base + k * s;
            if (i < n4) __stcs(out + i, __ldcs(in + i));
        }
    }
}

__global__ __launch_bounds__(256) void identity_copy_tail(
    const float* __restrict__ in, float* __restrict__ out, int start, int n)
{
    int i = start + blockIdx.x * blockDim.x + threadIdx.x;
    if (i < n) out[i] = in[i];
}

extern "C" void kernel_launch(void* const* d_in, const int* in_sizes, int n_in,
                              void* d_out, int out_size)
{
    const float* x = (const float*)d_in[0];
    float* out = (float*)d_out;
    int n = in_sizes[0];           // 33,554,432 (8 * 4096 * 1024)

    int n4 = n / 4;                // 8,388,608 float4
    if (n4 > 0) {
        const int threads = 128;
        const int per_block = threads * 2;             // 256 float4 / block
        int blocks = (n4 + per_block - 1) / per_block; // 32768
        identity_copy_f4x2_b128<<<blocks, threads>>>(
            (const float4*)x, (float4*)out, n4);
    }
    int tail_start = n4 * 4;
    if (n - tail_start > 0) {
        identity_copy_tail<<<1, 256>>>(x, out, tail_start, n);
    }
}

// round 15
// speedup vs baseline: 1.0383x; 1.0007x over previous
#include <cuda_runtime.h>
#include <cstdint>

// FourierFFTLayer == identity (ifft(fft(x)).real, rel_err ~1.3e-7 << 1e-3).
// HBM-bound copy at the ~7.5 TB/s path-independent LTS ceiling (~94% of
// spec). Last cache-policy probe: __ldlu (last-use) loads — line may be
// invalidated immediately after the read, freeing L2 slots for the .cs
// write stream without waiting for eviction. Shape unchanged from the
// measured optimum: MLP=2/thread, 128 threads x 32768 blocks.

__global__ __launch_bounds__(128) void identity_copy_f4x2_lu(
    const float4* __restrict__ in, float4* __restrict__ out, int n4)
{
    int base = blockIdx.x * (blockDim.x * 2) + threadIdx.x;
    const int s = blockDim.x;

    if (base + s < n4) {
        float4 a = __ldlu(in + base);
        float4 b = __ldlu(in + base + s);
        __stcs(out + base,     a);
        __stcs(out + base + s, b);
    } else {
        #pragma unroll
        for (int k = 0; k < 2; k++) {
            int i = base + k * s;
            if (i < n4) __stcs(out + i, __ldlu(in + i));
        }
    }
}

__global__ __launch_bounds__(256) void identity_copy_tail(
    const float* __restrict__ in, float* __restrict__ out, int start, int n)
{
    int i = start + blockIdx.x * blockDim.x + threadIdx.x;
    if (i < n) out[i] = in[i];
}

extern "C" void kernel_launch(void* const* d_in, const int* in_sizes, int n_in,
                              void* d_out, int out_size)
{
    const float* x = (const float*)d_in[0];
    float* out = (float*)d_out;
    int n = in_sizes[0];           // 33,554,432 (8 * 4096 * 1024)

    int n4 = n / 4;                // 8,388,608 float4
    if (n4 > 0) {
        const int threads = 128;
        const int per_block = threads * 2;             // 256 float4 / block
        int blocks = (n4 + per_block - 1) / per_block; // 32768
        identity_copy_f4x2_lu<<<blocks, threads>>>(
            (const float4*)x, (float4*)out, n4);
    }
    int tail_start = n4 * 4;
    if (n - tail_start > 0) {
        identity_copy_tail<<<1, 256>>>(x, out, tail_start, n);
    }
}